// round 1
// baseline (speedup 1.0000x reference)
#include <cuda_runtime.h>

#define MAXN      262144
#define IN_FEATS  16

// Scratch (device globals — no allocation allowed)
__device__ float  g_deg[MAXN];
__device__ float  g_norm[MAXN];
__device__ float4 g_Us[MAXN];    // norm-prescaled X0·[M1|M2]
__device__ float2 g_XA[MAXN];    // X0·M0
__device__ float4 g_Vacc[MAXN];  // pass-1 accumulator
__device__ float2 g_Zs[MAXN];    // norm²-scaled M2-half of pass-1 result
__device__ float2 g_P1[MAXN];    // finalized P0·M1
__device__ float2 g_Tacc[MAXN];  // pass-2 accumulator
__device__ float  g_M0[32], g_M1[32], g_M2[32];  // [j*2+o]
__device__ int    g_is64;

// --- detect int32 vs int64 indices (values < 100000 => high words all 0) ---
__global__ void k_detect(const unsigned* __restrict__ w, int E) {
    __shared__ int s_any;
    if (threadIdx.x == 0) s_any = 0;
    __syncthreads();
    int limit = (E < 4096) ? E : 4096;
    for (int k = threadIdx.x; k < limit; k += blockDim.x)
        if (w[2 * k + 1] != 0u) s_any = 1;
    __syncthreads();
    if (threadIdx.x == 0) g_is64 = (s_any == 0) ? 1 : 0;
}

__device__ __forceinline__ int load_idx(const void* p, int e) {
    return g_is64 ? (int)__ldg((const long long*)p + e)
                  : __ldg((const int*)p + e);
}

// --- zero accumulators + compute folded weight matrices ---
__global__ void k_init(const float* __restrict__ W,
                       const float* __restrict__ lam, int N) {
    int i = blockIdx.x * blockDim.x + threadIdx.x;
    if (i < N) {
        g_deg[i]  = 0.0f;
        g_Vacc[i] = make_float4(0.f, 0.f, 0.f, 0.f);
        g_Tacc[i] = make_float2(0.f, 0.f);
    }
    if (blockIdx.x == 0 && threadIdx.x < 32) {
        int j = threadIdx.x >> 1, o = threadIdx.x & 1;
        float r = 2.0f / __ldg(lam);
        float A = __ldg(W + o * 48 + j);
        float B = __ldg(W + o * 48 + 16 + j);
        float C = __ldg(W + o * 48 + 32 + j);
        float rm1 = r - 1.0f;
        g_M0[threadIdx.x] = A + rm1 * B + (2.0f * rm1 * rm1 - 1.0f) * C;
        g_M1[threadIdx.x] = -r * B - 4.0f * r * rm1 * C;
        g_M2[threadIdx.x] = 2.0f * r * r * C;
    }
}

// --- degree count ---
__global__ void k_deg(const void* __restrict__ dstv, int E) {
    int e = blockIdx.x * blockDim.x + threadIdx.x;
    if (e >= E) return;
    atomicAdd(&g_deg[load_idx(dstv, e)], 1.0f);
}

// --- per-node: norm + projections U = X0·[M1|M2] (pre-scaled), XA = X0·M0 ---
__global__ void k_node(const float* __restrict__ x, int N) {
    int i = blockIdx.x * blockDim.x + threadIdx.x;
    if (i >= N) return;
    float nrm = rsqrtf(fmaxf(g_deg[i], 1.0f));
    g_norm[i] = nrm;
    float u0 = 0.f, u1 = 0.f, u2 = 0.f, u3 = 0.f, a0 = 0.f, a1 = 0.f;
    const float4* xr = (const float4*)(x + (size_t)i * IN_FEATS);
#pragma unroll
    for (int q = 0; q < 4; q++) {
        float4 xv = __ldg(xr + q);
        float vals[4] = {xv.x, xv.y, xv.z, xv.w};
#pragma unroll
        for (int t = 0; t < 4; t++) {
            int j = q * 4 + t;
            float xj = vals[t];
            a0 += xj * g_M0[2 * j];  a1 += xj * g_M0[2 * j + 1];
            u0 += xj * g_M1[2 * j];  u1 += xj * g_M1[2 * j + 1];
            u2 += xj * g_M2[2 * j];  u3 += xj * g_M2[2 * j + 1];
        }
    }
    g_Us[i] = make_float4(u0 * nrm, u1 * nrm, u2 * nrm, u3 * nrm);
    g_XA[i] = make_float2(a0, a1);
}

// --- propagation pass 1: Vacc[dst] += Us[src] (4 floats/edge) ---
__global__ void k_prop1(const void* __restrict__ srcv,
                        const void* __restrict__ dstv, int E) {
    int e = blockIdx.x * blockDim.x + threadIdx.x;
    if (e >= E) return;
    int s = load_idx(srcv, e);
    int d = load_idx(dstv, e);
    float4 u = __ldg(&g_Us[s]);
    float* vd = (float*)&g_Vacc[d];
    atomicAdd(vd + 0, u.x);
    atomicAdd(vd + 1, u.y);
    atomicAdd(vd + 2, u.z);
    atomicAdd(vd + 3, u.w);
}

// --- finalize pass 1: P1 = dst-norm'd M1 part; Zs = norm²·(M2 part) for pass 2 ---
__global__ void k_fin1(int N) {
    int i = blockIdx.x * blockDim.x + threadIdx.x;
    if (i >= N) return;
    float nrm = g_norm[i];
    float4 v  = g_Vacc[i];
    g_P1[i] = make_float2(v.x * nrm, v.y * nrm);
    float n2 = nrm * nrm;
    g_Zs[i] = make_float2(v.z * n2, v.w * n2);
}

// --- propagation pass 2: Tacc[dst] += Zs[src] (2 floats/edge) ---
__global__ void k_prop2(const void* __restrict__ srcv,
                        const void* __restrict__ dstv, int E) {
    int e = blockIdx.x * blockDim.x + threadIdx.x;
    if (e >= E) return;
    int s = load_idx(srcv, e);
    int d = load_idx(dstv, e);
    float2 z = __ldg(&g_Zs[s]);
    float* td = (float*)&g_Tacc[d];
    atomicAdd(td + 0, z.x);
    atomicAdd(td + 1, z.y);
}

// --- epilogue: h = relu(XA + P1 + norm·Tacc) ---
__global__ void k_out(float2* __restrict__ out, int N) {
    int i = blockIdx.x * blockDim.x + threadIdx.x;
    if (i >= N) return;
    float nrm = g_norm[i];
    float2 t = g_Tacc[i], p = g_P1[i], a = g_XA[i];
    out[i] = make_float2(fmaxf(a.x + p.x + t.x * nrm, 0.0f),
                         fmaxf(a.y + p.y + t.y * nrm, 0.0f));
}

extern "C" void kernel_launch(void* const* d_in, const int* in_sizes, int n_in,
                              void* d_out, int out_size) {
    const float* in_feat = (const float*)d_in[0];
    const float* W       = (const float*)d_in[1];
    const void*  src     = d_in[2];
    const void*  dst     = d_in[3];
    const float* lam     = (const float*)d_in[4];

    int N = in_sizes[0] / IN_FEATS;
    int E = in_sizes[2];
    const int TB = 256;
    int nb = (N + TB - 1) / TB;
    int eb = (E + TB - 1) / TB;

    k_detect<<<1, 256>>>((const unsigned*)src, E);
    k_init<<<nb, TB>>>(W, lam, N);
    k_deg<<<eb, TB>>>(dst, E);
    k_node<<<nb, TB>>>(in_feat, N);
    k_prop1<<<eb, TB>>>(src, dst, E);
    k_fin1<<<nb, TB>>>(N);
    k_prop2<<<eb, TB>>>(src, dst, E);
    k_out<<<(float2*)d_out ? nb : nb, TB>>>((float2*)d_out, N);
}

// round 2
// speedup vs baseline: 1.6288x; 1.6288x over previous
#include <cuda_runtime.h>

#define MAXN      262144
#define MAXE      3400000
#define IN_FEATS  16

// Scratch (device globals — no allocation allowed)
__device__ float  g_deg[MAXN];
__device__ float  g_norm[MAXN];
__device__ float4 g_Us[MAXN];    // norm-prescaled X0·[M1|M2]
__device__ float2 g_XA[MAXN];    // X0·M0
__device__ float4 g_Vacc[MAXN];  // pass-1 accumulator
__device__ float2 g_Zs[MAXN];    // norm²-scaled M2-half of pass-1 result
__device__ float2 g_P1[MAXN];    // finalized P0·M1
__device__ float2 g_Tacc[MAXN];  // pass-2 accumulator
__device__ float  g_M0[32], g_M1[32], g_M2[32];  // [j*2+o]
__device__ int    g_is64;
__device__ int2   g_edge[MAXE];  // packed (src, dst) int32

// --- detect int32 vs int64 indices (values < 100000 => high words all 0) ---
__global__ void k_detect(const unsigned* __restrict__ w, int E) {
    __shared__ int s_any;
    if (threadIdx.x == 0) s_any = 0;
    __syncthreads();
    int limit = (E < 4096) ? E : 4096;
    for (int k = threadIdx.x; k < limit; k += blockDim.x)
        if (w[2 * k + 1] != 0u) s_any = 1;
    __syncthreads();
    if (threadIdx.x == 0) g_is64 = (s_any == 0) ? 1 : 0;
}

// --- zero accumulators + compute folded weight matrices ---
__global__ void k_init(const float* __restrict__ W,
                       const float* __restrict__ lam, int N) {
    int i = blockIdx.x * blockDim.x + threadIdx.x;
    if (i < N) {
        g_deg[i]  = 0.0f;
        g_Vacc[i] = make_float4(0.f, 0.f, 0.f, 0.f);
        g_Tacc[i] = make_float2(0.f, 0.f);
    }
    if (blockIdx.x == 0 && threadIdx.x < 32) {
        int j = threadIdx.x >> 1, o = threadIdx.x & 1;
        float r = 2.0f / __ldg(lam);
        float A = __ldg(W + o * 48 + j);
        float B = __ldg(W + o * 48 + 16 + j);
        float C = __ldg(W + o * 48 + 32 + j);
        float rm1 = r - 1.0f;
        g_M0[threadIdx.x] = A + rm1 * B + (2.0f * rm1 * rm1 - 1.0f) * C;
        g_M1[threadIdx.x] = -r * B - 4.0f * r * rm1 * C;
        g_M2[threadIdx.x] = 2.0f * r * r * C;
    }
}

// --- pre-pass: int64/int32 -> packed int2 edges + degree count ---
__global__ void k_pre(const void* __restrict__ srcv,
                      const void* __restrict__ dstv, int E) {
    int e = blockIdx.x * blockDim.x + threadIdx.x;
    if (e >= E) return;
    int s, d;
    if (g_is64) {
        s = (int)__ldcs((const long long*)srcv + e);
        d = (int)__ldcs((const long long*)dstv + e);
    } else {
        s = __ldcs((const int*)srcv + e);
        d = __ldcs((const int*)dstv + e);
    }
    __stcs(&g_edge[e], make_int2(s, d));
    atomicAdd(&g_deg[d], 1.0f);
}

// --- per-node: norm + projections U = X0·[M1|M2] (pre-scaled), XA = X0·M0 ---
__global__ void k_node(const float* __restrict__ x, int N) {
    int i = blockIdx.x * blockDim.x + threadIdx.x;
    if (i >= N) return;
    float nrm = rsqrtf(fmaxf(g_deg[i], 1.0f));
    g_norm[i] = nrm;
    float u0 = 0.f, u1 = 0.f, u2 = 0.f, u3 = 0.f, a0 = 0.f, a1 = 0.f;
    const float4* xr = (const float4*)(x + (size_t)i * IN_FEATS);
#pragma unroll
    for (int q = 0; q < 4; q++) {
        float4 xv = __ldg(xr + q);
        float vals[4] = {xv.x, xv.y, xv.z, xv.w};
#pragma unroll
        for (int t = 0; t < 4; t++) {
            int j = q * 4 + t;
            float xj = vals[t];
            a0 += xj * g_M0[2 * j];  a1 += xj * g_M0[2 * j + 1];
            u0 += xj * g_M1[2 * j];  u1 += xj * g_M1[2 * j + 1];
            u2 += xj * g_M2[2 * j];  u3 += xj * g_M2[2 * j + 1];
        }
    }
    g_Us[i] = make_float4(u0 * nrm, u1 * nrm, u2 * nrm, u3 * nrm);
    g_XA[i] = make_float2(a0, a1);
}

// --- propagation pass 1: Vacc[dst] += Us[src]  (ONE float4 red per edge) ---
__global__ void k_prop1(int E) {
    int e = blockIdx.x * blockDim.x + threadIdx.x;
    if (e >= E) return;
    int2 ed = __ldcs(&g_edge[e]);
    float4 u = __ldg(&g_Us[ed.x]);
    atomicAdd(&g_Vacc[ed.y], u);
}

// --- finalize pass 1: P1 = dst-norm'd M1 part; Zs = norm²·(M2 part) for pass 2 ---
__global__ void k_fin1(int N) {
    int i = blockIdx.x * blockDim.x + threadIdx.x;
    if (i >= N) return;
    float nrm = g_norm[i];
    float4 v  = g_Vacc[i];
    g_P1[i] = make_float2(v.x * nrm, v.y * nrm);
    float n2 = nrm * nrm;
    g_Zs[i] = make_float2(v.z * n2, v.w * n2);
}

// --- propagation pass 2: Tacc[dst] += Zs[src]  (ONE float2 red per edge) ---
__global__ void k_prop2(int E) {
    int e = blockIdx.x * blockDim.x + threadIdx.x;
    if (e >= E) return;
    int2 ed = __ldcs(&g_edge[e]);
    float2 z = __ldg(&g_Zs[ed.x]);
    atomicAdd(&g_Tacc[ed.y], z);
}

// --- epilogue: h = relu(XA + P1 + norm·Tacc) ---
__global__ void k_out(float2* __restrict__ out, int N) {
    int i = blockIdx.x * blockDim.x + threadIdx.x;
    if (i >= N) return;
    float nrm = g_norm[i];
    float2 t = g_Tacc[i], p = g_P1[i], a = g_XA[i];
    out[i] = make_float2(fmaxf(a.x + p.x + t.x * nrm, 0.0f),
                         fmaxf(a.y + p.y + t.y * nrm, 0.0f));
}

extern "C" void kernel_launch(void* const* d_in, const int* in_sizes, int n_in,
                              void* d_out, int out_size) {
    const float* in_feat = (const float*)d_in[0];
    const float* W       = (const float*)d_in[1];
    const void*  src     = d_in[2];
    const void*  dst     = d_in[3];
    const float* lam     = (const float*)d_in[4];

    int N = in_sizes[0] / IN_FEATS;
    int E = in_sizes[2];
    const int TB = 256;
    int nb = (N + TB - 1) / TB;
    int eb = (E + TB - 1) / TB;

    k_detect<<<1, 256>>>((const unsigned*)src, E);
    k_init<<<nb, TB>>>(W, lam, N);
    k_pre<<<eb, TB>>>(src, dst, E);
    k_node<<<nb, TB>>>(in_feat, N);
    k_prop1<<<eb, TB>>>(E);
    k_fin1<<<nb, TB>>>(N);
    k_prop2<<<eb, TB>>>(E);
    k_out<<<nb, TB>>>((float2*)d_out, N);
}